// round 14
// baseline (speedup 1.0000x reference)
#include <cuda_runtime.h>
#include <cuda_bf16.h>
#include <cuda_fp16.h>
#include <cstdint>
#include <cstddef>

#define NROWS_MAX 16384
#define DDIM 256            // K bytes per row (fp8)
#define TILE 128
#define ROWB 272            // padded smem row bytes -> conflict-free ldmatrix
#define TILE_SMEM (TILE*ROWB)          // 34816
#define SMEM_BYTES (4*TILE_SMEM)       // A + B0 + B1 + B2 = 139264 -> 1 CTA/SM
#define NTHREADS 256        // 8 warps -> 255-reg budget
#define CHUNK_T 16          // B tiles per work item

// f16x2 constants: exactly representable in f16
#define KH2 0x4D274D27u     // half2(20.609375)   ~ log2(e)/0.07
#define CH2 0xC49CC49Cu     // half2(-4.609375)   offset folded for f16 range
// stored rowsum = true_rowsum * 2^(Ch + Kt), Kt = 20.60992915555662
#define LOG_CORR 11.09073901f   // (20.60992915555662 - 4.609375) * ln2

__device__ __align__(16) uint8_t g_Xq[(size_t)NROWS_MAX*DDIM];
__device__ __align__(16) uint8_t g_Yq[(size_t)NROWS_MAX*DDIM];
__device__ float g_Sv[NROWS_MAX];
__device__ float g_rowsum[NROWS_MAX];
__device__ unsigned int g_sync;   // epoch grid barrier (monotonic, replay-safe)
__device__ unsigned int g_done;   // epoch last-CTA detector (monotonic)

static __device__ __forceinline__ uint32_t su32(const void* p){
    return (uint32_t)__cvta_generic_to_shared(p);
}
static __device__ __forceinline__ void cp16(uint32_t dst, const void* src){
    asm volatile("cp.async.cg.shared.global [%0], [%1], 16;\n" :: "r"(dst), "l"(src));
}
static __device__ __forceinline__ void cp_commit(){
    asm volatile("cp.async.commit_group;\n");
}
template<int N> static __device__ __forceinline__ void cp_wait(){
    asm volatile("cp.async.wait_group %0;\n" :: "n"(N));
}
static __device__ __forceinline__ uint16_t cvt_e4m3x2(float hi, float lo){
    uint16_t r;
    asm("cvt.rn.satfinite.e4m3x2.f32 %0, %1, %2;" : "=h"(r) : "f"(hi), "f"(lo));
    return r;
}
static __device__ __forceinline__ void ldsm4(uint32_t* r, uint32_t addr){
    asm volatile("ldmatrix.sync.aligned.m8n8.x4.shared.b16 {%0,%1,%2,%3}, [%4];"
        : "=r"(r[0]),"=r"(r[1]),"=r"(r[2]),"=r"(r[3]) : "r"(addr));
}
// fp8 e4m3 MMA with f16 accumulator (2 regs D/C)
static __device__ __forceinline__ void mma_fp8h(uint32_t* c, const uint32_t* a, const uint32_t* b){
    asm volatile(
        "mma.sync.aligned.m16n8k32.row.col.f16.e4m3.e4m3.f16 "
        "{%0,%1}, {%2,%3,%4,%5}, {%6,%7}, {%0,%1};\n"
        : "+r"(c[0]),"+r"(c[1])
        : "r"(a[0]),"r"(a[1]),"r"(a[2]),"r"(a[3]), "r"(b[0]),"r"(b[1]));
}
// epilogue triple for one f16x2 element: e = 2^(v*Kh+Ch); sum += e; v = 0
static __device__ __forceinline__ void epi_elem(uint32_t& v, uint32_t& sum){
    uint32_t e;
    asm("fma.rn.f16x2 %0, %1, %2, %3;" : "=r"(e) : "r"(v), "r"(KH2), "r"(CH2));
    asm("ex2.approx.f16x2 %0, %1;" : "=r"(e) : "r"(e));
    asm("add.rn.f16x2 %0, %0, %1;" : "+r"(sum) : "r"(e));
    v = 0u;
}

// ---------------- fused single kernel: prep | grid barrier | GEMM | loss ----------------
__global__ void __launch_bounds__(NTHREADS, 1) lit_fused_kernel(
    const float* __restrict__ X, const float* __restrict__ Y,
    float* __restrict__ out, int nrows, int items, int nTrow)
{
    extern __shared__ char sm[];
    __shared__ float rowsum_sm[TILE];
    __shared__ double red_d[8];
    __shared__ bool s_last;

    const int tid  = threadIdx.x;
    const int lane = tid & 31, wid = tid >> 5;
    const int wm = wid >> 1, wn = wid & 1;       // 4x2 warp grid over 128x128
    const int g = lane >> 2, t = lane & 3;

    // ================= phase 1: normalize X,Y -> e4m3; Sv; zero rowsum =================
    {
        int gwarp  = blockIdx.x*(NTHREADS/32) + wid;
        int stride = gridDim.x*(NTHREADS/32);
        for (int row = gwarp; row < nrows; row += stride){
            const float4* xp = reinterpret_cast<const float4*>(X) + (size_t)row*(DDIM/4);
            const float4* yp = reinterpret_cast<const float4*>(Y) + (size_t)row*(DDIM/4);
            float4 x0 = xp[lane*2+0], x1 = xp[lane*2+1];
            float4 y0 = yp[lane*2+0], y1 = yp[lane*2+1];
            float ssx = x0.x*x0.x + x0.y*x0.y + x0.z*x0.z + x0.w*x0.w
                      + x1.x*x1.x + x1.y*x1.y + x1.z*x1.z + x1.w*x1.w;
            float ssy = y0.x*y0.x + y0.y*y0.y + y0.z*y0.z + y0.w*y0.w
                      + y1.x*y1.x + y1.y*y1.y + y1.z*y1.z + y1.w*y1.w;
            float dot = x0.x*y0.x + x0.y*y0.y + x0.z*y0.z + x0.w*y0.w
                      + x1.x*y1.x + x1.y*y1.y + x1.z*y1.z + x1.w*y1.w;
            #pragma unroll
            for (int o=16;o;o>>=1){
                ssx += __shfl_xor_sync(0xffffffffu, ssx, o);
                ssy += __shfl_xor_sync(0xffffffffu, ssy, o);
                dot += __shfl_xor_sync(0xffffffffu, dot, o);
            }
            float nx = fmaxf(sqrtf(ssx), 1e-12f);
            float ny = fmaxf(sqrtf(ssy), 1e-12f);
            float ivx = 1.0f/nx, ivy = 1.0f/ny;
            union { uint16_t q[4]; uint2 u; } pk;
            pk.q[0] = cvt_e4m3x2(x0.y*ivx, x0.x*ivx);
            pk.q[1] = cvt_e4m3x2(x0.w*ivx, x0.z*ivx);
            pk.q[2] = cvt_e4m3x2(x1.y*ivx, x1.x*ivx);
            pk.q[3] = cvt_e4m3x2(x1.w*ivx, x1.z*ivx);
            *reinterpret_cast<uint2*>(g_Xq + (size_t)row*DDIM + lane*8) = pk.u;
            pk.q[0] = cvt_e4m3x2(y0.y*ivy, y0.x*ivy);
            pk.q[1] = cvt_e4m3x2(y0.w*ivy, y0.z*ivy);
            pk.q[2] = cvt_e4m3x2(y1.y*ivy, y1.x*ivy);
            pk.q[3] = cvt_e4m3x2(y1.w*ivy, y1.z*ivy);
            *reinterpret_cast<uint2*>(g_Yq + (size_t)row*DDIM + lane*8) = pk.u;
            if (lane==0){
                g_Sv[row] = (dot/(nx*ny) - 1.0f) * 14.285714285714286f;
                g_rowsum[row] = 0.0f;
            }
        }
    }

    // ============ grid barrier (all CTAs resident; epoch-based, replay-safe) ============
    __syncthreads();
    if (tid == 0){
        __threadfence();                                  // release phase-1 writes
        unsigned int old = atomicAdd(&g_sync, 1u);
        unsigned int target = (old/gridDim.x + 1u) * gridDim.x;
        while (atomicAdd(&g_sync, 0u) < target) __nanosleep(64);
        __threadfence();                                  // acquire
    }
    __syncthreads();

    // ================= phase 2: persistent fused fp8 GEMM + exp2 + row-sum =============
    const uint32_t sA = su32(sm);
    const uint32_t sB = sA + TILE_SMEM;
    const uint32_t aoff = sA + (uint32_t)((wm*32 + (lane & 15))*ROWB + ((lane >> 4) & 1)*16);
    const uint32_t boff = (uint32_t)((wn*64 + (lane & 7) + ((lane >> 4) & 1)*8)*ROWB
                                     + ((lane >> 3) & 1)*16);

    for (int item = blockIdx.x; item < items; item += gridDim.x){
        const int rt = item % nTrow;          // row tile
        const int ch = item / nTrow;          // col chunk
        const uint8_t* Ychunk = g_Yq + (size_t)(ch * CHUNK_T)*TILE*DDIM;

        if (tid < TILE) rowsum_sm[tid] = 0.f;

        // prologue: 3 groups = A | B0 | B1
        {
            const uint8_t* Ag = g_Xq + (size_t)rt*TILE*DDIM;
            #pragma unroll
            for (int j=0;j<8;j++){
                int idx = tid + NTHREADS*j;
                int r = idx >> 4, c = idx & 15;
                cp16(sA + r*ROWB + c*16, Ag + r*DDIM + c*16);
            }
            cp_commit();   // group A
            #pragma unroll
            for (int j=0;j<8;j++){
                int idx = tid + NTHREADS*j;
                int r = idx >> 4, c = idx & 15;
                cp16(sB + r*ROWB + c*16, Ychunk + r*DDIM + c*16);
            }
            cp_commit();   // group B0
            #pragma unroll
            for (int j=0;j<8;j++){
                int idx = tid + NTHREADS*j;
                int r = idx >> 4, c = idx & 15;
                cp16(sB + TILE_SMEM + r*ROWB + c*16, Ychunk + TILE*DDIM + r*DDIM + c*16);
            }
            cp_commit();   // group B1
        }

        // A tile visible -> hoist all A fragments into registers (reused 16x)
        cp_wait<2>();
        __syncthreads();
        uint32_t afrag[64];
        #pragma unroll
        for (int ks=0; ks<8; ++ks){
            ldsm4(afrag + ks*8,     aoff + ks*32);
            ldsm4(afrag + ks*8 + 4, aoff + 16*ROWB + ks*32);
        }

        uint32_t acc[32];
        #pragma unroll
        for (int j=0;j<32;j++) acc[j] = 0u;
        float rowsum[4] = {0.f,0.f,0.f,0.f};

        for (int it = 0; it < CHUNK_T; ++it){
            // single collective point: tile `it` visible to ALL warps; readers of
            // buffer (it+2)%3 == (it-1)%3 are done -> prefetch is safe
            cp_wait<1>();
            __syncthreads();

            if (it + 2 < CHUNK_T){
                const uint8_t* Yg = Ychunk + (size_t)(it + 2)*TILE*DDIM;
                uint32_t bw = sB + (uint32_t)(((it+2)%3)*TILE_SMEM);
                #pragma unroll
                for (int j=0;j<8;j++){
                    int idx = tid + NTHREADS*j;
                    int r = idx >> 4, c = idx & 15;
                    cp16(bw + r*ROWB + c*16, Yg + r*DDIM + c*16);
                }
            }
            cp_commit();            // uniform: exactly one group per iteration

            const uint32_t bb = sB + (uint32_t)((it%3)*TILE_SMEM) + boff;

            #pragma unroll
            for (int ks=0; ks<8; ++ks){
                uint32_t b0[4], b1[4], b2[4], b3[4];   // N = 64 per warp
                ldsm4(b0, bb + ks*32);
                ldsm4(b1, bb + 16*ROWB + ks*32);
                ldsm4(b2, bb + 32*ROWB + ks*32);
                ldsm4(b3, bb + 48*ROWB + ks*32);
                const uint32_t* a0 = afrag + ks*8;
                const uint32_t* a1 = afrag + ks*8 + 4;
                mma_fp8h(acc + 0,  a0, b0 + 0);
                mma_fp8h(acc + 2,  a0, b0 + 2);
                mma_fp8h(acc + 4,  a0, b1 + 0);
                mma_fp8h(acc + 6,  a0, b1 + 2);
                mma_fp8h(acc + 8,  a0, b2 + 0);
                mma_fp8h(acc + 10, a0, b2 + 2);
                mma_fp8h(acc + 12, a0, b3 + 0);
                mma_fp8h(acc + 14, a0, b3 + 2);
                mma_fp8h(acc + 16, a1, b0 + 0);
                mma_fp8h(acc + 18, a1, b0 + 2);
                mma_fp8h(acc + 20, a1, b1 + 0);
                mma_fp8h(acc + 22, a1, b1 + 2);
                mma_fp8h(acc + 24, a1, b2 + 0);
                mma_fp8h(acc + 26, a1, b2 + 2);
                mma_fp8h(acc + 28, a1, b3 + 0);
                mma_fp8h(acc + 30, a1, b3 + 2);
            }

            // serial f16x2 epilogue: e = 2^(s*Kh+Ch), per-slot sums, reset acc
            uint32_t sum2[4] = {0u,0u,0u,0u};
            #pragma unroll
            for (int r=0;r<32;r++){
                int s = ((r >> 4) << 1) | (r & 1);
                epi_elem(acc[r], sum2[s]);
            }
            #pragma unroll
            for (int s=0;s<4;s++){
                __half2 h = *reinterpret_cast<__half2*>(&sum2[s]);
                rowsum[s] += __low2float(h) + __high2float(h);
            }
        }

        // merge: reduce over t lanes, then across wn warps via smem atomics
        #pragma unroll
        for (int s=0;s<4;s++){
            rowsum[s] += __shfl_xor_sync(0xffffffffu, rowsum[s], 1);
            rowsum[s] += __shfl_xor_sync(0xffffffffu, rowsum[s], 2);
        }
        if (t == 0){
            #pragma unroll
            for (int s=0;s<4;s++){
                int r = wm*32 + (s>>1)*16 + (s&1)*8 + g;
                atomicAdd(&rowsum_sm[r], rowsum[s]);
            }
        }
        __syncthreads();
        if (tid < TILE) atomicAdd(&g_rowsum[rt*TILE + tid], rowsum_sm[tid]);
        __syncthreads();
    }

    // ================= phase 3: last CTA computes the loss =================
    if (tid == 0){
        __threadfence();                                 // release my rowsum atomics
        unsigned int old = atomicAdd(&g_done, 1u);
        s_last = ((old + 1u) % gridDim.x) == 0u;
    }
    __syncthreads();
    if (s_last){
        __threadfence();                                 // acquire all CTAs' rowsums
        double s = 0.0;
        for (int i = tid; i < nrows; i += NTHREADS){
            float rs = __ldcg(&g_rowsum[i]);
            float sv = __ldcg(&g_Sv[i]);
            s += (double)(logf(rs) - LOG_CORR - sv);
        }
        #pragma unroll
        for (int o=16;o;o>>=1) s += __shfl_xor_sync(0xffffffffu, s, o);
        if (lane == 0) red_d[wid] = s;
        __syncthreads();
        if (tid == 0){
            double tot = 0.0;
            #pragma unroll
            for (int w=0;w<8;w++) tot += red_d[w];
            out[0] = (float)(tot / (double)nrows);
        }
    }
}

extern "C" void kernel_launch(void* const* d_in, const int* in_sizes, int n_in,
                              void* d_out, int out_size){
    const float* X = (const float*)d_in[0];   // text_features
    const float* Y = (const float*)d_in[1];   // image_features
    float* out = (float*)d_out;
    int nrows = in_sizes[0] / DDIM;

    int nsm = 148;
    cudaDeviceGetAttribute(&nsm, cudaDevAttrMultiProcessorCount, 0);

    int nTrow = nrows / TILE;                  // 128
    int nchunk = nTrow / CHUNK_T;              // 8
    if (nchunk < 1) nchunk = 1;
    int items = nTrow * nchunk;                // 1024

    cudaFuncSetAttribute(lit_fused_kernel,
                         cudaFuncAttributeMaxDynamicSharedMemorySize, SMEM_BYTES);
    lit_fused_kernel<<<nsm, NTHREADS, SMEM_BYTES>>>(X, Y, out, nrows, items, nTrow);
}

// round 15
// speedup vs baseline: 1.0825x; 1.0825x over previous
#include <cuda_runtime.h>
#include <cuda_bf16.h>
#include <cuda_fp16.h>
#include <cstdint>
#include <cstddef>

#define NROWS_MAX 16384
#define DDIM 256            // K bytes per row (fp8)
#define TILE 128
#define ROWB 272            // padded smem row bytes -> conflict-free ldmatrix
#define TILE_SMEM (TILE*ROWB)          // 34816
#define SMEM_BYTES (4*TILE_SMEM)       // A + B0 + B1 + B2 = 139264
#define NTHREADS 256        // 8 warps -> 255-reg budget

// f16x2 constants: exactly representable in f16
#define KH2 0x4D274D27u     // half2(20.609375)   ~ log2(e)/0.07
#define CH2 0xC49CC49Cu     // half2(-4.609375)   offset folded for f16 range
// stored rowsum = true_rowsum * 2^(Ch + Kt), Kt = 20.60992915555662
#define LOG_CORR 11.09073901f   // (20.60992915555662 - 4.609375) * ln2

__device__ __align__(16) uint8_t g_Xq[(size_t)NROWS_MAX*DDIM];
__device__ __align__(16) uint8_t g_Yq[(size_t)NROWS_MAX*DDIM];
__device__ float g_Sv[NROWS_MAX];
__device__ float g_rowsum[NROWS_MAX];
__device__ unsigned int g_done;   // epoch last-CTA detector (monotonic, replay-safe)

static __device__ __forceinline__ uint32_t su32(const void* p){
    return (uint32_t)__cvta_generic_to_shared(p);
}
static __device__ __forceinline__ void cp16(uint32_t dst, const void* src){
    asm volatile("cp.async.cg.shared.global [%0], [%1], 16;\n" :: "r"(dst), "l"(src));
}
static __device__ __forceinline__ void cp_commit(){
    asm volatile("cp.async.commit_group;\n");
}
template<int N> static __device__ __forceinline__ void cp_wait(){
    asm volatile("cp.async.wait_group %0;\n" :: "n"(N));
}
static __device__ __forceinline__ uint16_t cvt_e4m3x2(float hi, float lo){
    uint16_t r;
    asm("cvt.rn.satfinite.e4m3x2.f32 %0, %1, %2;" : "=h"(r) : "f"(hi), "f"(lo));
    return r;
}
static __device__ __forceinline__ void ldsm4(uint32_t* r, uint32_t addr){
    asm volatile("ldmatrix.sync.aligned.m8n8.x4.shared.b16 {%0,%1,%2,%3}, [%4];"
        : "=r"(r[0]),"=r"(r[1]),"=r"(r[2]),"=r"(r[3]) : "r"(addr));
}
// fp8 e4m3 MMA with f16 accumulator (2 regs D/C)
static __device__ __forceinline__ void mma_fp8h(uint32_t* c, const uint32_t* a, const uint32_t* b){
    asm volatile(
        "mma.sync.aligned.m16n8k32.row.col.f16.e4m3.e4m3.f16 "
        "{%0,%1}, {%2,%3,%4,%5}, {%6,%7}, {%0,%1};\n"
        : "+r"(c[0]),"+r"(c[1])
        : "r"(a[0]),"r"(a[1]),"r"(a[2]),"r"(a[3]), "r"(b[0]),"r"(b[1]));
}
// epilogue triple for one f16x2 element: e = 2^(v*Kh+Ch); sum += e; v = 0
static __device__ __forceinline__ void epi_elem(uint32_t& v, uint32_t& sum){
    uint32_t e;
    asm("fma.rn.f16x2 %0, %1, %2, %3;" : "=r"(e) : "r"(v), "r"(KH2), "r"(CH2));
    asm("ex2.approx.f16x2 %0, %1;" : "=r"(e) : "r"(e));
    asm("add.rn.f16x2 %0, %0, %1;" : "+r"(sum) : "r"(e));
    v = 0u;
}

// ------- prep: normalize X,Y -> e4m3 rows, Sv=(dot-1)/t, zero rowsum -------
__global__ void prep_kernel(const float* __restrict__ X, const float* __restrict__ Y,
                            int nrows){
    int gw   = (blockIdx.x*blockDim.x + threadIdx.x) >> 5;
    int lane = threadIdx.x & 31;
    if (gw >= nrows) return;
    const float4* xp = reinterpret_cast<const float4*>(X) + (size_t)gw*(DDIM/4);
    const float4* yp = reinterpret_cast<const float4*>(Y) + (size_t)gw*(DDIM/4);
    float4 x0 = xp[lane*2+0], x1 = xp[lane*2+1];
    float4 y0 = yp[lane*2+0], y1 = yp[lane*2+1];
    float ssx = x0.x*x0.x + x0.y*x0.y + x0.z*x0.z + x0.w*x0.w
              + x1.x*x1.x + x1.y*x1.y + x1.z*x1.z + x1.w*x1.w;
    float ssy = y0.x*y0.x + y0.y*y0.y + y0.z*y0.z + y0.w*y0.w
              + y1.x*y1.x + y1.y*y1.y + y1.z*y1.z + y1.w*y1.w;
    float dot = x0.x*y0.x + x0.y*y0.y + x0.z*y0.z + x0.w*y0.w
              + x1.x*y1.x + x1.y*y1.y + x1.z*y1.z + x1.w*y1.w;
    #pragma unroll
    for (int o=16;o;o>>=1){
        ssx += __shfl_xor_sync(0xffffffffu, ssx, o);
        ssy += __shfl_xor_sync(0xffffffffu, ssy, o);
        dot += __shfl_xor_sync(0xffffffffu, dot, o);
    }
    float nx = fmaxf(sqrtf(ssx), 1e-12f);
    float ny = fmaxf(sqrtf(ssy), 1e-12f);
    float ivx = 1.0f / nx, ivy = 1.0f / ny;
    union { uint16_t q[4]; uint2 u; } pk;
    pk.q[0] = cvt_e4m3x2(x0.y*ivx, x0.x*ivx);
    pk.q[1] = cvt_e4m3x2(x0.w*ivx, x0.z*ivx);
    pk.q[2] = cvt_e4m3x2(x1.y*ivx, x1.x*ivx);
    pk.q[3] = cvt_e4m3x2(x1.w*ivx, x1.z*ivx);
    *reinterpret_cast<uint2*>(g_Xq + (size_t)gw*DDIM + lane*8) = pk.u;
    pk.q[0] = cvt_e4m3x2(y0.y*ivy, y0.x*ivy);
    pk.q[1] = cvt_e4m3x2(y0.w*ivy, y0.z*ivy);
    pk.q[2] = cvt_e4m3x2(y1.y*ivy, y1.x*ivy);
    pk.q[3] = cvt_e4m3x2(y1.w*ivy, y1.z*ivy);
    *reinterpret_cast<uint2*>(g_Yq + (size_t)gw*DDIM + lane*8) = pk.u;
    if (lane==0){
        g_Sv[gw] = (dot/(nx*ny) - 1.0f) * 14.285714285714286f;
        g_rowsum[gw] = 0.0f;
    }
}

// ---------------- main: balanced-range fused fp8 GEMM + exp2 + row-sum + loss ----------
// CTA b processes contiguous flattened tiles [b*total/grid, (b+1)*total/grid):
// at most 108 tiles/CTA, at most 2 row-tile segments. Last CTA computes the loss.
__global__ void __launch_bounds__(NTHREADS, 1) lit_main_kernel(
    float* __restrict__ out, int nrows, int nTcol)
{
    extern __shared__ char sm[];
    __shared__ float rowsum_sm[TILE];
    __shared__ double red_d[8];
    __shared__ bool s_last;

    const int tid  = threadIdx.x;
    const int lane = tid & 31, wid = tid >> 5;
    const int wm = wid >> 1, wn = wid & 1;       // 4x2 warp grid over 128x128
    const int g = lane >> 2, t = lane & 3;

    const uint32_t sA = su32(sm);
    const uint32_t sB = sA + TILE_SMEM;
    const uint32_t aoff = sA + (uint32_t)((wm*32 + (lane & 15))*ROWB + ((lane >> 4) & 1)*16);
    const uint32_t boff = (uint32_t)((wn*64 + (lane & 7) + ((lane >> 4) & 1)*8)*ROWB
                                     + ((lane >> 3) & 1)*16);

    const int total = (nrows/TILE) * nTcol;
    int cur = (int)(((long long)blockIdx.x     * total) / gridDim.x);
    const int rend = (int)(((long long)(blockIdx.x+1) * total) / gridDim.x);

    while (cur < rend){
        const int rt  = cur / nTcol;
        const int ct0 = cur - rt*nTcol;
        int segEnd = (rt+1)*nTcol; if (segEnd > rend) segEnd = rend;
        const int nT = segEnd - cur;          // 1..128 tiles in this segment
        const uint8_t* Ybase = g_Yq + (size_t)ct0*TILE*DDIM;

        if (tid < TILE) rowsum_sm[tid] = 0.f;

        // prologue: 3 groups = A | B0 | B1 (B1 empty when nT==1)
        {
            const uint8_t* Ag = g_Xq + (size_t)rt*TILE*DDIM;
            #pragma unroll
            for (int j=0;j<8;j++){
                int idx = tid + NTHREADS*j;
                int r = idx >> 4, c = idx & 15;
                cp16(sA + r*ROWB + c*16, Ag + r*DDIM + c*16);
            }
            cp_commit();   // group A
            #pragma unroll
            for (int j=0;j<8;j++){
                int idx = tid + NTHREADS*j;
                int r = idx >> 4, c = idx & 15;
                cp16(sB + r*ROWB + c*16, Ybase + r*DDIM + c*16);
            }
            cp_commit();   // group B0
            if (nT > 1){
                #pragma unroll
                for (int j=0;j<8;j++){
                    int idx = tid + NTHREADS*j;
                    int r = idx >> 4, c = idx & 15;
                    cp16(sB + TILE_SMEM + r*ROWB + c*16, Ybase + TILE*DDIM + r*DDIM + c*16);
                }
            }
            cp_commit();   // group B1 (possibly empty)
        }

        // A tile visible -> hoist all A fragments into registers (reused nT times)
        cp_wait<2>();
        __syncthreads();
        uint32_t afrag[64];
        #pragma unroll
        for (int ks=0; ks<8; ++ks){
            ldsm4(afrag + ks*8,     aoff + ks*32);
            ldsm4(afrag + ks*8 + 4, aoff + 16*ROWB + ks*32);
        }

        uint32_t acc[32];
        #pragma unroll
        for (int j=0;j<32;j++) acc[j] = 0u;
        float rowsum[4] = {0.f,0.f,0.f,0.f};

        for (int it = 0; it < nT; ++it){
            // single collective point: tile `it` visible to ALL warps; readers of
            // buffer (it+2)%3 == (it-1)%3 are done -> prefetch is safe
            cp_wait<1>();
            __syncthreads();

            if (it + 2 < nT){
                const uint8_t* Yg = Ybase + (size_t)(it + 2)*TILE*DDIM;
                uint32_t bw = sB + (uint32_t)(((it+2)%3)*TILE_SMEM);
                #pragma unroll
                for (int j=0;j<8;j++){
                    int idx = tid + NTHREADS*j;
                    int r = idx >> 4, c = idx & 15;
                    cp16(bw + r*ROWB + c*16, Yg + r*DDIM + c*16);
                }
            }
            cp_commit();            // uniform: exactly one group per iteration

            const uint32_t bb = sB + (uint32_t)((it%3)*TILE_SMEM) + boff;

            #pragma unroll
            for (int ks=0; ks<8; ++ks){
                uint32_t b0[4], b1[4], b2[4], b3[4];   // N = 64 per warp
                ldsm4(b0, bb + ks*32);
                ldsm4(b1, bb + 16*ROWB + ks*32);
                ldsm4(b2, bb + 32*ROWB + ks*32);
                ldsm4(b3, bb + 48*ROWB + ks*32);
                const uint32_t* a0 = afrag + ks*8;
                const uint32_t* a1 = afrag + ks*8 + 4;
                mma_fp8h(acc + 0,  a0, b0 + 0);
                mma_fp8h(acc + 2,  a0, b0 + 2);
                mma_fp8h(acc + 4,  a0, b1 + 0);
                mma_fp8h(acc + 6,  a0, b1 + 2);
                mma_fp8h(acc + 8,  a0, b2 + 0);
                mma_fp8h(acc + 10, a0, b2 + 2);
                mma_fp8h(acc + 12, a0, b3 + 0);
                mma_fp8h(acc + 14, a0, b3 + 2);
                mma_fp8h(acc + 16, a1, b0 + 0);
                mma_fp8h(acc + 18, a1, b0 + 2);
                mma_fp8h(acc + 20, a1, b1 + 0);
                mma_fp8h(acc + 22, a1, b1 + 2);
                mma_fp8h(acc + 24, a1, b2 + 0);
                mma_fp8h(acc + 26, a1, b2 + 2);
                mma_fp8h(acc + 28, a1, b3 + 0);
                mma_fp8h(acc + 30, a1, b3 + 2);
            }

            // serial f16x2 epilogue: e = 2^(s*Kh+Ch), per-slot sums, reset acc
            uint32_t sum2[4] = {0u,0u,0u,0u};
            #pragma unroll
            for (int r=0;r<32;r++){
                int s = ((r >> 4) << 1) | (r & 1);
                epi_elem(acc[r], sum2[s]);
            }
            #pragma unroll
            for (int s=0;s<4;s++){
                __half2 h = *reinterpret_cast<__half2*>(&sum2[s]);
                rowsum[s] += __low2float(h) + __high2float(h);
            }
        }

        // drain outstanding groups before next segment's prologue reuses buffers
        cp_wait<0>();
        __syncthreads();

        // merge: reduce over t lanes, then across wn warps via smem atomics
        #pragma unroll
        for (int s=0;s<4;s++){
            rowsum[s] += __shfl_xor_sync(0xffffffffu, rowsum[s], 1);
            rowsum[s] += __shfl_xor_sync(0xffffffffu, rowsum[s], 2);
        }
        if (t == 0){
            #pragma unroll
            for (int s=0;s<4;s++){
                int r = wm*32 + (s>>1)*16 + (s&1)*8 + g;
                atomicAdd(&rowsum_sm[r], rowsum[s]);
            }
        }
        __syncthreads();
        if (tid < TILE) atomicAdd(&g_rowsum[rt*TILE + tid], rowsum_sm[tid]);
        __syncthreads();

        cur = segEnd;
    }

    // ---------------- last CTA computes the loss ----------------
    if (tid == 0){
        __threadfence();                                 // release my rowsum atomics
        unsigned int old = atomicAdd(&g_done, 1u);
        s_last = ((old + 1u) % gridDim.x) == 0u;
    }
    __syncthreads();
    if (s_last){
        __threadfence();                                 // acquire all CTAs' rowsums
        double s = 0.0;
        for (int i = tid; i < nrows; i += NTHREADS){
            float rs = __ldcg(&g_rowsum[i]);
            float sv = __ldcg(&g_Sv[i]);
            s += (double)(logf(rs) - LOG_CORR - sv);
        }
        #pragma unroll
        for (int o=16;o;o>>=1) s += __shfl_xor_sync(0xffffffffu, s, o);
        if (lane == 0) red_d[wid] = s;
        __syncthreads();
        if (tid == 0){
            double tot = 0.0;
            #pragma unroll
            for (int w=0;w<8;w++) tot += red_d[w];
            out[0] = (float)(tot / (double)nrows);
        }
    }
}

extern "C" void kernel_launch(void* const* d_in, const int* in_sizes, int n_in,
                              void* d_out, int out_size){
    const float* X = (const float*)d_in[0];   // text_features
    const float* Y = (const float*)d_in[1];   // image_features
    float* out = (float*)d_out;
    int nrows = in_sizes[0] / DDIM;

    int nsm = 148;
    cudaDeviceGetAttribute(&nsm, cudaDevAttrMultiProcessorCount, 0);

    int nb = (nrows*32 + 255) / 256;
    prep_kernel<<<nb, 256>>>(X, Y, nrows);

    int nTcol = nrows / TILE;                  // 128
    cudaFuncSetAttribute(lit_main_kernel,
                         cudaFuncAttributeMaxDynamicSharedMemorySize, SMEM_BYTES);
    lit_main_kernel<<<nsm, NTHREADS, SMEM_BYTES>>>(out, nrows, nTcol);
}

// round 16
// speedup vs baseline: 1.1073x; 1.0228x over previous
#include <cuda_runtime.h>
#include <cuda_bf16.h>
#include <cuda_fp16.h>
#include <cstdint>
#include <cstddef>

#define NROWS_MAX 16384
#define DDIM 256            // K bytes per row (fp8)
#define TILE 128
#define ROWB 272            // padded smem row bytes -> conflict-free ldmatrix
#define TILE_SMEM (TILE*ROWB)          // 34816
#define SMEM_BYTES (4*TILE_SMEM)       // A + B0 + B1 + B2 = 139264
#define NTHREADS 256        // 8 warps -> 255-reg budget
#define NRT_MAX (NROWS_MAX/TILE)       // 128 row tiles

// f16x2 constants: exactly representable in f16
#define KH2 0x4D274D27u     // half2(20.609375)   ~ log2(e)/0.07
#define CH2 0xC49CC49Cu     // half2(-4.609375)   offset folded for f16 range
// stored rowsum = true_rowsum * 2^(Ch + Kt), Kt = 20.60992915555662
#define LOG_CORR 11.09073901f   // (20.60992915555662 - 4.609375) * ln2

__device__ __align__(16) uint8_t g_Xq[(size_t)NROWS_MAX*DDIM];
__device__ __align__(16) uint8_t g_Yq[(size_t)NROWS_MAX*DDIM];
__device__ float g_Sv[NROWS_MAX];
__device__ float g_rowsum[NROWS_MAX];
__device__ double g_acc;
__device__ unsigned int g_rt_count[NRT_MAX];  // column tiles accumulated per row tile
__device__ unsigned int g_tdone;              // finished row tiles

static __device__ __forceinline__ uint32_t su32(const void* p){
    return (uint32_t)__cvta_generic_to_shared(p);
}
static __device__ __forceinline__ void cp16(uint32_t dst, const void* src){
    asm volatile("cp.async.cg.shared.global [%0], [%1], 16;\n" :: "r"(dst), "l"(src));
}
static __device__ __forceinline__ void cp_commit(){
    asm volatile("cp.async.commit_group;\n");
}
template<int N> static __device__ __forceinline__ void cp_wait(){
    asm volatile("cp.async.wait_group %0;\n" :: "n"(N));
}
static __device__ __forceinline__ uint16_t cvt_e4m3x2(float hi, float lo){
    uint16_t r;
    asm("cvt.rn.satfinite.e4m3x2.f32 %0, %1, %2;" : "=h"(r) : "f"(hi), "f"(lo));
    return r;
}
static __device__ __forceinline__ void ldsm4(uint32_t* r, uint32_t addr){
    asm volatile("ldmatrix.sync.aligned.m8n8.x4.shared.b16 {%0,%1,%2,%3}, [%4];"
        : "=r"(r[0]),"=r"(r[1]),"=r"(r[2]),"=r"(r[3]) : "r"(addr));
}
// fp8 e4m3 MMA with f16 accumulator (2 regs D/C)
static __device__ __forceinline__ void mma_fp8h(uint32_t* c, const uint32_t* a, const uint32_t* b){
    asm volatile(
        "mma.sync.aligned.m16n8k32.row.col.f16.e4m3.e4m3.f16 "
        "{%0,%1}, {%2,%3,%4,%5}, {%6,%7}, {%0,%1};\n"
        : "+r"(c[0]),"+r"(c[1])
        : "r"(a[0]),"r"(a[1]),"r"(a[2]),"r"(a[3]), "r"(b[0]),"r"(b[1]));
}
// epilogue triple for one f16x2 element: e = 2^(v*Kh+Ch); sum += e; v = 0
static __device__ __forceinline__ void epi_elem(uint32_t& v, uint32_t& sum){
    uint32_t e;
    asm("fma.rn.f16x2 %0, %1, %2, %3;" : "=r"(e) : "r"(v), "r"(KH2), "r"(CH2));
    asm("ex2.approx.f16x2 %0, %1;" : "=r"(e) : "r"(e));
    asm("add.rn.f16x2 %0, %0, %1;" : "+r"(sum) : "r"(e));
    v = 0u;
}

// ------- prep: normalize X,Y -> e4m3 rows, Sv=(dot-1)/t, zero rowsum/counters -------
__global__ void prep_kernel(const float* __restrict__ X, const float* __restrict__ Y,
                            int nrows){
    if (blockIdx.x == 0 && threadIdx.x < NRT_MAX){
        g_rt_count[threadIdx.x] = 0u;
        if (threadIdx.x == 0){ g_acc = 0.0; g_tdone = 0u; }
    }
    int gw   = (blockIdx.x*blockDim.x + threadIdx.x) >> 5;
    int lane = threadIdx.x & 31;
    if (gw >= nrows) return;
    const float4* xp = reinterpret_cast<const float4*>(X) + (size_t)gw*(DDIM/4);
    const float4* yp = reinterpret_cast<const float4*>(Y) + (size_t)gw*(DDIM/4);
    float4 x0 = xp[lane*2+0], x1 = xp[lane*2+1];
    float4 y0 = yp[lane*2+0], y1 = yp[lane*2+1];
    float ssx = x0.x*x0.x + x0.y*x0.y + x0.z*x0.z + x0.w*x0.w
              + x1.x*x1.x + x1.y*x1.y + x1.z*x1.z + x1.w*x1.w;
    float ssy = y0.x*y0.x + y0.y*y0.y + y0.z*y0.z + y0.w*y0.w
              + y1.x*y1.x + y1.y*y1.y + y1.z*y1.z + y1.w*y1.w;
    float dot = x0.x*y0.x + x0.y*y0.y + x0.z*y0.z + x0.w*y0.w
              + x1.x*y1.x + x1.y*y1.y + x1.z*y1.z + x1.w*y1.w;
    #pragma unroll
    for (int o=16;o;o>>=1){
        ssx += __shfl_xor_sync(0xffffffffu, ssx, o);
        ssy += __shfl_xor_sync(0xffffffffu, ssy, o);
        dot += __shfl_xor_sync(0xffffffffu, dot, o);
    }
    float nx = fmaxf(sqrtf(ssx), 1e-12f);
    float ny = fmaxf(sqrtf(ssy), 1e-12f);
    float ivx = 1.0f / nx, ivy = 1.0f / ny;
    union { uint16_t q[4]; uint2 u; } pk;
    pk.q[0] = cvt_e4m3x2(x0.y*ivx, x0.x*ivx);
    pk.q[1] = cvt_e4m3x2(x0.w*ivx, x0.z*ivx);
    pk.q[2] = cvt_e4m3x2(x1.y*ivx, x1.x*ivx);
    pk.q[3] = cvt_e4m3x2(x1.w*ivx, x1.z*ivx);
    *reinterpret_cast<uint2*>(g_Xq + (size_t)gw*DDIM + lane*8) = pk.u;
    pk.q[0] = cvt_e4m3x2(y0.y*ivy, y0.x*ivy);
    pk.q[1] = cvt_e4m3x2(y0.w*ivy, y0.z*ivy);
    pk.q[2] = cvt_e4m3x2(y1.y*ivy, y1.x*ivy);
    pk.q[3] = cvt_e4m3x2(y1.w*ivy, y1.z*ivy);
    *reinterpret_cast<uint2*>(g_Yq + (size_t)gw*DDIM + lane*8) = pk.u;
    if (lane==0){
        g_Sv[gw] = (dot/(nx*ny) - 1.0f) * 14.285714285714286f;
        g_rowsum[gw] = 0.0f;
    }
}

// ---------------- main: balanced-range fused fp8 GEMM + exp2 + row-sum ----------
// CTA b processes contiguous flattened tiles [b*total/grid, (b+1)*total/grid).
// Loss is computed incrementally: the CTA that completes the last column
// contribution of a row tile immediately folds that tile's 128 loss terms into
// g_acc (overlapped with other CTAs' GEMM). The CTA finishing the last row
// tile writes out[0].
__global__ void __launch_bounds__(NTHREADS, 1) lit_main_kernel(
    float* __restrict__ out, int nrows, int nTcol)
{
    extern __shared__ char sm[];
    __shared__ float rowsum_sm[TILE];
    __shared__ double red_d[8];
    __shared__ bool s_fin, s_out;

    const int tid  = threadIdx.x;
    const int lane = tid & 31, wid = tid >> 5;
    const int wm = wid >> 1, wn = wid & 1;       // 4x2 warp grid over 128x128
    const int g = lane >> 2, t = lane & 3;
    const int nTrow = nrows / TILE;

    const uint32_t sA = su32(sm);
    const uint32_t sB = sA + TILE_SMEM;
    const uint32_t aoff = sA + (uint32_t)((wm*32 + (lane & 15))*ROWB + ((lane >> 4) & 1)*16);
    const uint32_t boff = (uint32_t)((wn*64 + (lane & 7) + ((lane >> 4) & 1)*8)*ROWB
                                     + ((lane >> 3) & 1)*16);

    const int total = nTrow * nTcol;
    int cur = (int)(((long long)blockIdx.x     * total) / gridDim.x);
    const int rend = (int)(((long long)(blockIdx.x+1) * total) / gridDim.x);

    while (cur < rend){
        const int rt  = cur / nTcol;
        const int ct0 = cur - rt*nTcol;
        int segEnd = (rt+1)*nTcol; if (segEnd > rend) segEnd = rend;
        const int nT = segEnd - cur;          // 1..nTcol tiles in this segment
        const uint8_t* Ybase = g_Yq + (size_t)ct0*TILE*DDIM;

        if (tid < TILE) rowsum_sm[tid] = 0.f;

        // prologue: 3 groups = A | B0 | B1 (B1 empty when nT==1)
        {
            const uint8_t* Ag = g_Xq + (size_t)rt*TILE*DDIM;
            #pragma unroll
            for (int j=0;j<8;j++){
                int idx = tid + NTHREADS*j;
                int r = idx >> 4, c = idx & 15;
                cp16(sA + r*ROWB + c*16, Ag + r*DDIM + c*16);
            }
            cp_commit();   // group A
            #pragma unroll
            for (int j=0;j<8;j++){
                int idx = tid + NTHREADS*j;
                int r = idx >> 4, c = idx & 15;
                cp16(sB + r*ROWB + c*16, Ybase + r*DDIM + c*16);
            }
            cp_commit();   // group B0
            if (nT > 1){
                #pragma unroll
                for (int j=0;j<8;j++){
                    int idx = tid + NTHREADS*j;
                    int r = idx >> 4, c = idx & 15;
                    cp16(sB + TILE_SMEM + r*ROWB + c*16, Ybase + TILE*DDIM + r*DDIM + c*16);
                }
            }
            cp_commit();   // group B1 (possibly empty)
        }

        // A tile visible -> hoist all A fragments into registers (reused nT times)
        cp_wait<2>();
        __syncthreads();
        uint32_t afrag[64];
        #pragma unroll
        for (int ks=0; ks<8; ++ks){
            ldsm4(afrag + ks*8,     aoff + ks*32);
            ldsm4(afrag + ks*8 + 4, aoff + 16*ROWB + ks*32);
        }

        uint32_t acc[32];
        #pragma unroll
        for (int j=0;j<32;j++) acc[j] = 0u;
        float rowsum[4] = {0.f,0.f,0.f,0.f};

        for (int it = 0; it < nT; ++it){
            // single collective point: tile `it` visible to ALL warps; readers of
            // buffer (it+2)%3 == (it-1)%3 are done -> prefetch is safe
            cp_wait<1>();
            __syncthreads();

            if (it + 2 < nT){
                const uint8_t* Yg = Ybase + (size_t)(it + 2)*TILE*DDIM;
                uint32_t bw = sB + (uint32_t)(((it+2)%3)*TILE_SMEM);
                #pragma unroll
                for (int j=0;j<8;j++){
                    int idx = tid + NTHREADS*j;
                    int r = idx >> 4, c = idx & 15;
                    cp16(bw + r*ROWB + c*16, Yg + r*DDIM + c*16);
                }
            }
            cp_commit();            // uniform: exactly one group per iteration

            const uint32_t bb = sB + (uint32_t)((it%3)*TILE_SMEM) + boff;

            #pragma unroll
            for (int ks=0; ks<8; ++ks){
                uint32_t b0[4], b1[4], b2[4], b3[4];   // N = 64 per warp
                ldsm4(b0, bb + ks*32);
                ldsm4(b1, bb + 16*ROWB + ks*32);
                ldsm4(b2, bb + 32*ROWB + ks*32);
                ldsm4(b3, bb + 48*ROWB + ks*32);
                const uint32_t* a0 = afrag + ks*8;
                const uint32_t* a1 = afrag + ks*8 + 4;
                mma_fp8h(acc + 0,  a0, b0 + 0);
                mma_fp8h(acc + 2,  a0, b0 + 2);
                mma_fp8h(acc + 4,  a0, b1 + 0);
                mma_fp8h(acc + 6,  a0, b1 + 2);
                mma_fp8h(acc + 8,  a0, b2 + 0);
                mma_fp8h(acc + 10, a0, b2 + 2);
                mma_fp8h(acc + 12, a0, b3 + 0);
                mma_fp8h(acc + 14, a0, b3 + 2);
                mma_fp8h(acc + 16, a1, b0 + 0);
                mma_fp8h(acc + 18, a1, b0 + 2);
                mma_fp8h(acc + 20, a1, b1 + 0);
                mma_fp8h(acc + 22, a1, b1 + 2);
                mma_fp8h(acc + 24, a1, b2 + 0);
                mma_fp8h(acc + 26, a1, b2 + 2);
                mma_fp8h(acc + 28, a1, b3 + 0);
                mma_fp8h(acc + 30, a1, b3 + 2);
            }

            // serial f16x2 epilogue: e = 2^(s*Kh+Ch), per-slot sums, reset acc
            uint32_t sum2[4] = {0u,0u,0u,0u};
            #pragma unroll
            for (int r=0;r<32;r++){
                int s = ((r >> 4) << 1) | (r & 1);
                epi_elem(acc[r], sum2[s]);
            }
            #pragma unroll
            for (int s=0;s<4;s++){
                __half2 h = *reinterpret_cast<__half2*>(&sum2[s]);
                rowsum[s] += __low2float(h) + __high2float(h);
            }
        }

        // drain outstanding groups before next segment's prologue reuses buffers
        cp_wait<0>();
        __syncthreads();

        // merge: reduce over t lanes, then across wn warps via smem atomics
        #pragma unroll
        for (int s=0;s<4;s++){
            rowsum[s] += __shfl_xor_sync(0xffffffffu, rowsum[s], 1);
            rowsum[s] += __shfl_xor_sync(0xffffffffu, rowsum[s], 2);
        }
        if (t == 0){
            #pragma unroll
            for (int s=0;s<4;s++){
                int r = wm*32 + (s>>1)*16 + (s&1)*8 + g;
                atomicAdd(&rowsum_sm[r], rowsum[s]);
            }
        }
        __syncthreads();
        if (tid < TILE) atomicAdd(&g_rowsum[rt*TILE + tid], rowsum_sm[tid]);
        __syncthreads();

        // counter-gated incremental loss for this row tile
        if (tid == 0){
            __threadfence();   // release my rowsum contributions
            unsigned int c = atomicAdd(&g_rt_count[rt], (unsigned int)nT);
            s_fin = (c + (unsigned int)nT == (unsigned int)nTcol);
            s_out = false;
        }
        __syncthreads();
        if (s_fin){
            __threadfence();   // acquire all contributions to this row tile
            double v = 0.0;
            if (tid < TILE){
                float rs = __ldcg(&g_rowsum[rt*TILE + tid]);
                float sv = __ldcg(&g_Sv[rt*TILE + tid]);
                v = (double)(logf(rs) - LOG_CORR - sv);
            }
            #pragma unroll
            for (int o=16;o;o>>=1) v += __shfl_xor_sync(0xffffffffu, v, o);
            if (lane == 0) red_d[wid] = v;
            __syncthreads();
            if (tid == 0){
                double tv = 0.0;
                #pragma unroll
                for (int w=0;w<8;w++) tv += red_d[w];
                atomicAdd(&g_acc, tv);
                __threadfence();   // release my g_acc add
                unsigned int d = atomicAdd(&g_tdone, 1u);
                s_out = (d + 1u == (unsigned int)nTrow);
            }
            __syncthreads();
            if (s_out && tid == 0){
                __threadfence();   // acquire all g_acc adds
                double tot;
                asm volatile("ld.global.cg.f64 %0, [%1];" : "=d"(tot) : "l"(&g_acc));
                out[0] = (float)(tot / (double)nrows);
            }
        }
        __syncthreads();   // rowsum_sm / red_d reuse safety for next segment

        cur = segEnd;
    }
}

extern "C" void kernel_launch(void* const* d_in, const int* in_sizes, int n_in,
                              void* d_out, int out_size){
    const float* X = (const float*)d_in[0];   // text_features
    const float* Y = (const float*)d_in[1];   // image_features
    float* out = (float*)d_out;
    int nrows = in_sizes[0] / DDIM;

    int nsm = 148;
    cudaDeviceGetAttribute(&nsm, cudaDevAttrMultiProcessorCount, 0);

    int nb = (nrows*32 + 255) / 256;
    prep_kernel<<<nb, 256>>>(X, Y, nrows);

    int nTcol = nrows / TILE;                  // 128
    cudaFuncSetAttribute(lit_main_kernel,
                         cudaFuncAttributeMaxDynamicSharedMemorySize, SMEM_BYTES);
    lit_main_kernel<<<nsm, NTHREADS, SMEM_BYTES>>>(out, nrows, nTcol);
}